// round 16
// baseline (speedup 1.0000x reference)
#include <cuda_runtime.h>
#include <cuda_bf16.h>
#include <math.h>

#define Bb_ 2
#define H_ 480
#define W_ 480
#define C_ 32
#define BC 64
#define HP 500
#define WN_ 20
#define NM 40           // 40 ky modes (20 low + 20 high)
#define NPIX (H_*W_)    // 230400
#define NROWS (BC*H_)   // 30720
#define KSPLIT 12       // h-split (480 = 12*40)
#define NPART 12
#define WSPLIT 4        // k_fft_w w-split (480 = 4*120)

typedef unsigned long long u64;

__device__ __forceinline__ u64 pack2(float lo, float hi) {
    u64 r; asm("mov.b64 %0, {%1, %2};" : "=l"(r) : "f"(lo), "f"(hi)); return r;
}
__device__ __forceinline__ void unpack2(u64 v, float& lo, float& hi) {
    asm("mov.b64 {%0, %1}, %2;" : "=f"(lo), "=f"(hi) : "l"(v));
}
__device__ __forceinline__ void fma2(u64& d, u64 a, u64 b) {
    asm("fma.rn.f32x2 %0, %1, %2, %0;" : "+l"(d) : "l"(a), "l"(b));
}

// ---------------- device scratch (static; no allocations) ----------------
__device__ float g_bufA[BC*NPIX];         // 59 MB
__device__ float g_bufB[BC*NPIX];         // 59 MB
__device__ float g_E[BC*NPIX];            // 59 MB
__device__ float g_S1[WSPLIT*NROWS*40];   // w-split partials: [q][row][kz]
__device__ float g_S2p[NPART*BC*1600];    // h-split partials: [sp][bc][1600]
__device__ float g_S2[BC*1600];           // summed: [bc][m][kx][z]
__device__ float g_S3[BC*NM*WN_*2];       // [b][o][m][kx][z]
__device__ float g_T[NROWS*40];           // [bc*480+h][kz] (scaled)
__device__ float g_Wt[W_*40];             // fwd w-twiddle: [w][2kx+z] (z=1 -> -sin)
__device__ float g_Wh[NM*H_*2];           // ky twiddle: [m][h]{cos,sin}
__device__ float g_Gi[40*W_];             // inv w-twiddle rows: [2kx+z][w] (z=1 -> -sin)

__device__ __forceinline__ float gelu_f(float x) {
    return 0.5f * x * (1.0f + erff(x * 0.70710678118654752f));
}

// ---------------- trig tables ----------------
__global__ void k_tables() {
    int t = blockIdx.x * blockDim.x + threadIdx.x;
    if (t < W_ * 40) {
        int c = t % 40, w = t / 40;
        int kx = c >> 1;
        int idx = (kx * w) % 500;
        float s, cc;
        sincospif(2.0f * (float)idx / 500.0f, &s, &cc);
        g_Wt[t] = (c & 1) ? -s : cc;
    }
    if (t < NM * H_) {
        int h = t % H_, m = t / H_;
        int ky = (m < 20) ? m : (460 + m);
        int idx = (ky * h) % 500;
        float s, cc;
        sincospif(2.0f * (float)idx / 500.0f, &s, &cc);
        g_Wh[t * 2] = cc;
        g_Wh[t * 2 + 1] = s;
    }
    if (t < 40 * W_) {
        int w = t % W_, kz = t / W_;
        int kx = kz >> 1;
        int idx = (kx * w) % 500;
        float s, cc;
        sincospif(2.0f * (float)idx / 500.0f, &s, &cc);
        g_Gi[t] = (kz & 1) ? -s : cc;
    }
}

// ---------------- encoder: two tiny MLPs -> A0, E (2-pixel tile, shared weights) --------
__global__ void __launch_bounds__(256) k_encode(
        const float* __restrict__ input, const float* __restrict__ src,
        const float* __restrict__ iw1, const float* __restrict__ ib1,
        const float* __restrict__ iw2, const float* __restrict__ ib2,
        const float* __restrict__ ew1, const float* __restrict__ eb1,
        const float* __restrict__ ew2, const float* __restrict__ eb2,
        float* __restrict__ A, float* __restrict__ E) {
    __shared__ __align__(16) float siw1[5][16];
    __shared__ __align__(16) float sib1[16];
    __shared__ __align__(16) float siw2[16][32];
    __shared__ __align__(16) float sib2[32];
    __shared__ __align__(16) float sew1[3][16];
    __shared__ __align__(16) float seb1[16];
    __shared__ __align__(16) float sew2[16][32];
    __shared__ __align__(16) float seb2[32];
    int tid = threadIdx.x;
    if (tid < 80) (&siw1[0][0])[tid] = iw1[tid];
    if (tid >= 80 && tid < 96) sib1[tid - 80] = ib1[tid - 80];
    if (tid >= 96 && tid < 144) (&sew1[0][0])[tid - 96] = ew1[tid - 96];
    if (tid >= 144 && tid < 160) seb1[tid - 144] = eb1[tid - 144];
    if (tid >= 160 && tid < 192) sib2[tid - 160] = ib2[tid - 160];
    if (tid >= 192 && tid < 224) seb2[tid - 192] = eb2[tid - 192];
    for (int e = tid; e < 512; e += 256) {
        (&siw2[0][0])[e] = iw2[e];
        (&sew2[0][0])[e] = ew2[e];
    }
    __syncthreads();

    int p0 = (blockIdx.x * 256 + tid) * 2;
    int w = p0 % W_;
    int h = (p0 / W_) % H_;
    int b = p0 / NPIX;
    int hw = h * W_ + w;
    float gx = (float)h * (1.0f / 479.0f);
    float gy0 = (float)w * (1.0f / 479.0f);
    float gy1 = (float)(w + 1) * (1.0f / 479.0f);

    const float* sp = src + (size_t)p0 * 3;
    float2 s01 = *(const float2*)sp;
    float2 s23 = *(const float2*)(sp + 2);
    float2 s45 = *(const float2*)(sp + 4);
    float xin0[5] = { s01.x, s01.y, s23.x, gx, gy0 };
    float xin1[5] = { s23.y, s45.x, s45.y, gx, gy1 };
    float2 iv = *(const float2*)&input[(size_t)p0];
    float xe0[3] = { iv.x, gx, gy0 };
    float xe1[3] = { iv.y, gx, gy1 };

    // ---- in-MLP ----
    {
        u64 hp0[8], hp1[8];
#pragma unroll
        for (int jp = 0; jp < 8; jp++) {
            u64 bp = *(const u64*)&sib1[jp * 2];
            hp0[jp] = bp; hp1[jp] = bp;
        }
#pragma unroll
        for (int f = 0; f < 5; f++) {
            u64 x0 = pack2(xin0[f], xin0[f]);
            u64 x1 = pack2(xin1[f], xin1[f]);
#pragma unroll
            for (int jp = 0; jp < 8; jp++) {
                u64 wp = *(const u64*)&siw1[f][jp * 2];
                fma2(hp0[jp], x0, wp);
                fma2(hp1[jp], x1, wp);
            }
        }
        float hid0[16], hid1[16];
#pragma unroll
        for (int jp = 0; jp < 8; jp++) {
            float a, bb;
            unpack2(hp0[jp], a, bb);
            hid0[jp * 2] = gelu_f(a); hid0[jp * 2 + 1] = gelu_f(bb);
            unpack2(hp1[jp], a, bb);
            hid1[jp * 2] = gelu_f(a); hid1[jp * 2 + 1] = gelu_f(bb);
        }
#pragma unroll
        for (int ch = 0; ch < 2; ch++) {
            int c0 = ch * 16;
            u64 acc0[8], acc1[8];
#pragma unroll
            for (int cp = 0; cp < 8; cp++) {
                u64 bp = *(const u64*)&sib2[c0 + cp * 2];
                acc0[cp] = bp; acc1[cp] = bp;
            }
#pragma unroll
            for (int j = 0; j < 16; j++) {
                u64 h0 = pack2(hid0[j], hid0[j]);
                u64 h1 = pack2(hid1[j], hid1[j]);
#pragma unroll
                for (int cp = 0; cp < 8; cp++) {
                    u64 wp = *(const u64*)&siw2[j][c0 + cp * 2];
                    fma2(acc0[cp], h0, wp);
                    fma2(acc1[cp], h1, wp);
                }
            }
#pragma unroll
            for (int cp = 0; cp < 8; cp++) {
                float a0lo, a0hi, a1lo, a1hi;
                unpack2(acc0[cp], a0lo, a0hi);
                unpack2(acc1[cp], a1lo, a1hi);
                int clo = c0 + cp * 2;
                *(float2*)&A[((size_t)(b * C_ + clo)) * NPIX + hw] = make_float2(a0lo, a1lo);
                *(float2*)&A[((size_t)(b * C_ + clo + 1)) * NPIX + hw] = make_float2(a0hi, a1hi);
            }
        }
    }
    // ---- eps-MLP ----
    {
        u64 hp0[8], hp1[8];
#pragma unroll
        for (int jp = 0; jp < 8; jp++) {
            u64 bp = *(const u64*)&seb1[jp * 2];
            hp0[jp] = bp; hp1[jp] = bp;
        }
#pragma unroll
        for (int f = 0; f < 3; f++) {
            u64 x0 = pack2(xe0[f], xe0[f]);
            u64 x1 = pack2(xe1[f], xe1[f]);
#pragma unroll
            for (int jp = 0; jp < 8; jp++) {
                u64 wp = *(const u64*)&sew1[f][jp * 2];
                fma2(hp0[jp], x0, wp);
                fma2(hp1[jp], x1, wp);
            }
        }
        float hid0[16], hid1[16];
#pragma unroll
        for (int jp = 0; jp < 8; jp++) {
            float a, bb;
            unpack2(hp0[jp], a, bb);
            hid0[jp * 2] = gelu_f(a); hid0[jp * 2 + 1] = gelu_f(bb);
            unpack2(hp1[jp], a, bb);
            hid1[jp * 2] = gelu_f(a); hid1[jp * 2 + 1] = gelu_f(bb);
        }
#pragma unroll
        for (int ch = 0; ch < 2; ch++) {
            int c0 = ch * 16;
            u64 acc0[8], acc1[8];
#pragma unroll
            for (int cp = 0; cp < 8; cp++) {
                u64 bp = *(const u64*)&seb2[c0 + cp * 2];
                acc0[cp] = bp; acc1[cp] = bp;
            }
#pragma unroll
            for (int j = 0; j < 16; j++) {
                u64 h0 = pack2(hid0[j], hid0[j]);
                u64 h1 = pack2(hid1[j], hid1[j]);
#pragma unroll
                for (int cp = 0; cp < 8; cp++) {
                    u64 wp = *(const u64*)&sew2[j][c0 + cp * 2];
                    fma2(acc0[cp], h0, wp);
                    fma2(acc1[cp], h1, wp);
                }
            }
#pragma unroll
            for (int cp = 0; cp < 8; cp++) {
                float a0lo, a0hi, a1lo, a1hi;
                unpack2(acc0[cp], a0lo, a0hi);
                unpack2(acc1[cp], a1lo, a1hi);
                int clo = c0 + cp * 2;
                *(float2*)&E[((size_t)(b * C_ + clo)) * NPIX + hw] = make_float2(a0lo, a1lo);
                *(float2*)&E[((size_t)(b * C_ + clo + 1)) * NPIX + hw] = make_float2(a0hi, a1hi);
            }
        }
    }
}

// ---------------- stage 1 forward: per-row w-DFT, 4-way w-split, FFMA2, f4 staging -----
#define FW_BM 96
#define FW_BK 40
__global__ void __launch_bounds__(160) k_fft_w(const float* __restrict__ A,
                                               const float* __restrict__ E,
                                               float* __restrict__ S1p) {
    __shared__ float sp[FW_BM][44];
    __shared__ float st[FW_BK][40];
    int tid = threadIdx.x;
    int q = blockIdx.y;                 // quarter 0..3, 120 w each
    int row0 = blockIdx.x * FW_BM;
    int bc = row0 / H_;
    int hbase = row0 % H_;
    const float* abase = A + (size_t)bc * NPIX + hbase * W_ + q * 120;
    const float* ebase = E + (size_t)bc * NPIX + hbase * W_ + q * 120;
    int tx = tid % 10;
    int ty = tid / 10;
    u64 accP[6][2];
#pragma unroll
    for (int i = 0; i < 6; i++) { accP[i][0] = 0ULL; accP[i][1] = 0ULL; }

    for (int k0 = 0; k0 < 120; k0 += FW_BK) {
        for (int e = tid; e < FW_BM * 10; e += 160) {
            int r = e / 10, k4 = e % 10;
            float4 a = *(const float4*)&abase[r * W_ + k0 + k4 * 4];
            float4 ev = *(const float4*)&ebase[r * W_ + k0 + k4 * 4];
            float4 pv = make_float4(a.x * ev.x, a.y * ev.y, a.z * ev.z, a.w * ev.w);
            *(float4*)&sp[r][k4 * 4] = pv;
        }
        {
            const float* wt = g_Wt + (q * 120 + k0) * 40;
            for (int e = tid; e < FW_BK * 10; e += 160) {
                int row = e / 10, c4 = e % 10;
                *(float4*)&st[row][c4 * 4] = *(const float4*)&wt[row * 40 + c4 * 4];
            }
        }
        __syncthreads();
#pragma unroll
        for (int kk = 0; kk < FW_BK; kk += 4) {
            float avf[6][4];
            ulonglong2 bq[4];
#pragma unroll
            for (int i = 0; i < 6; i++)
                *(float4*)avf[i] = *(const float4*)&sp[ty * 6 + i][kk];
#pragma unroll
            for (int t = 0; t < 4; t++)
                bq[t] = *(const ulonglong2*)&st[kk + t][tx * 4];
#pragma unroll
            for (int t = 0; t < 4; t++) {
#pragma unroll
                for (int i = 0; i < 6; i++) {
                    u64 a2 = pack2(avf[i][t], avf[i][t]);
                    fma2(accP[i][0], a2, bq[t].x);
                    fma2(accP[i][1], a2, bq[t].y);
                }
            }
        }
        __syncthreads();
    }
#pragma unroll
    for (int i = 0; i < 6; i++) {
        int r = row0 + ty * 6 + i;
        float4 v;
        unpack2(accP[i][0], v.x, v.y);
        unpack2(accP[i][1], v.z, v.w);
        *(float4*)&S1p[((size_t)q * NROWS + r) * 40 + tx * 4] = v;
    }
}

// ---------------- stage 2 forward: ky-DFT, planar FFMA2, in-block reduction ----------------
// grid (BC, 12); block 400 = 4 subtiles(10h) x 20 m-groups(2) x 5 kx-groups(4)
__global__ void __launch_bounds__(400) k_fft_h(const float* __restrict__ S1p,
                                               float* __restrict__ S2p) {
    __shared__ __align__(16) float pool[1600 + 1600 + 6560];
    float* s1re = pool;             // [40][20]
    float* s1im = pool + 1600;      // [40][20]
    float* w4   = pool + 3200;      // [40][41][4] {c,c,s,s}; reused as reduction buf
    int bc = blockIdx.x;
    int spg = blockIdx.y;
    int t = threadIdx.x;
    int h0 = spg * 40;
    const float* base = S1p + (size_t)(bc * H_) * 40;
    const size_t qstride = (size_t)NROWS * 40;

    for (int e = t; e < 800; e += 400) {
        int hh = e / 20, kx = e % 20;
        size_t off = (size_t)(h0 + hh) * 40 + kx * 2;
        float2 a = *(const float2*)&base[off];
        float2 b = *(const float2*)&base[qstride + off];
        float2 c = *(const float2*)&base[2 * qstride + off];
        float2 d = *(const float2*)&base[3 * qstride + off];
        s1re[hh * 20 + kx] = (a.x + b.x) + (c.x + d.x);
        s1im[hh * 20 + kx] = (a.y + b.y) + (c.y + d.y);
    }
    for (int e = t; e < 1600; e += 400) {
        int m = e / 40, hh = e % 40;
        float2 w = *(const float2*)&g_Wh[(m * H_ + h0 + hh) * 2];
        *(float4*)&w4[(m * 41 + hh) * 4] = make_float4(w.x, w.x, w.y, w.y);
    }
    __syncthreads();

    int sub = t / 100;           // 4 subtiles of 10 h
    int r = t % 100;
    int mg = r / 5;              // 20 m-groups of 2
    int kxg = r % 5;             // 5 kx-groups of 4 kx (2 u64 pairs)
    int m0 = mg * 2;
    u64 AR[2][2], AC[2][2], AS[2][2];
#pragma unroll
    for (int mi = 0; mi < 2; mi++)
#pragma unroll
        for (int j = 0; j < 2; j++) { AR[mi][j] = 0ULL; AC[mi][j] = 0ULL; AS[mi][j] = 0ULL; }

#pragma unroll
    for (int hh = 0; hh < 10; hh++) {
        int hl = sub * 10 + hh;
        ulonglong2 REq = *(const ulonglong2*)&s1re[hl * 20 + kxg * 4];
        ulonglong2 IMq = *(const ulonglong2*)&s1im[hl * 20 + kxg * 4];
#pragma unroll
        for (int mi = 0; mi < 2; mi++) {
            ulonglong2 wq = *(const ulonglong2*)&w4[((m0 + mi) * 41 + hl) * 4]; // {c,c},{s,s}
            fma2(AR[mi][0], REq.x, wq.x);
            fma2(AR[mi][1], REq.y, wq.x);
            fma2(AR[mi][0], IMq.x, wq.y);
            fma2(AR[mi][1], IMq.y, wq.y);
            fma2(AC[mi][0], IMq.x, wq.x);
            fma2(AC[mi][1], IMq.y, wq.x);
            fma2(AS[mi][0], REq.x, wq.y);
            fma2(AS[mi][1], REq.y, wq.y);
        }
    }
    __syncthreads();   // all w4 reads done; safe to overwrite with partials

#pragma unroll
    for (int mi = 0; mi < 2; mi++) {
#pragma unroll
        for (int jj = 0; jj < 2; jj++) {
            float ar0, ar1, c0, c1, s0, s1v;
            unpack2(AR[mi][jj], ar0, ar1);
            unpack2(AC[mi][jj], c0, c1);
            unpack2(AS[mi][jj], s0, s1v);
            float4 v = make_float4(ar0, c0 - s0, ar1, c1 - s1v);
            *(float4*)&w4[t * 16 + mi * 8 + jj * 4] = v;
        }
    }
    __syncthreads();

    size_t obase = ((size_t)spg * BC + bc) * 1600;
#pragma unroll
    for (int gofs = 0; gofs < 4; gofs++) {
        int g = t + gofs * 400;
        int m = g / 40;
        int rem = g % 40;
        int kx2 = rem / 4;
        int qq = rem % 4;
        int rr = (m / 2) * 5 + kx2 / 2;
        int j = (m % 2) * 8 + (kx2 % 2) * 4 + qq;
        float a = 0.f;
#pragma unroll
        for (int sb = 0; sb < 4; sb++)
            a += w4[(sb * 100 + rr) * 16 + j];
        S2p[obase + g] = a;
    }
}

// ---------------- reduce split partials (float4) ----------------
__global__ void k_red(const float* __restrict__ P, float* __restrict__ S) {
    int t = blockIdx.x * blockDim.x + threadIdx.x;
    if (t >= BC * 1600 / 4) return;
    float4 a = make_float4(0.f, 0.f, 0.f, 0.f);
#pragma unroll
    for (int p = 0; p < NPART; p++) {
        float4 v = *(const float4*)&P[(size_t)p * BC * 1600 + t * 4];
        a.x += v.x; a.y += v.y; a.z += v.z; a.w += v.w;
    }
    *(float4*)&S[t * 4] = a;
}

// ---------------- mode mixing ----------------
__global__ void k_mix(const float* __restrict__ S2, const float* __restrict__ fw1,
                      const float* __restrict__ fw2, int l, float* __restrict__ S3) {
    int t = blockIdx.x * blockDim.x + threadIdx.x;
    if (t >= Bb_ * C_ * NM * WN_ * 2) return;
    int z = t & 1;
    int kx = (t >> 1) % WN_;
    int m = ((t >> 1) / WN_) % NM;
    int o = ((t >> 1) / (WN_ * NM)) % C_;
    int b = t / (2 * WN_ * NM * C_);
    const float* wb;
    if (m < 20) wb = fw1 + l * 819200 + o * 800 + m * 40 + kx * 2 + z;
    else        wb = fw2 + l * 819200 + o * 800 + (m - 20) * 40 + kx * 2 + z;
    const float* s2 = S2 + (b * C_) * 1600 + m * (WN_ * 2) + kx * 2 + z;
    float acc = 0.f;
#pragma unroll 8
    for (int i = 0; i < C_; i++)
        acc += s2[i * 1600] * wb[i * 25600];
    S3[((b * C_ + o) * NM + m) * (WN_ * 2) + kx * 2 + z] = acc;
}

// ---------------- stage 1 inverse: ky synthesis, planar FFMA2 shared tiles ----------------
// grid (BC, 12); block 400 = 40 h x 10 kx-pairs
__global__ void __launch_bounds__(400) k_ifft_h(const float* __restrict__ S3,
                                                float* __restrict__ T) {
    __shared__ __align__(16) float pool[1600 + 1600 + 6560];
    float* s3re = pool;             // [40 m][20 kx]
    float* s3im = pool + 1600;      // [40 m][20 kx]
    float* w4   = pool + 3200;      // [40 m][41 hh][4] {c,c,s,s}
    int bc = blockIdx.x;
    int spg = blockIdx.y;
    int t = threadIdx.x;
    int h0 = spg * 40;
    const float* s3 = S3 + (size_t)bc * 1600;

    for (int e = t; e < 800; e += 400) {
        int m = e / 20, kx = e % 20;
        float2 a = *(const float2*)&s3[m * 40 + kx * 2];
        s3re[m * 20 + kx] = a.x;
        s3im[m * 20 + kx] = a.y;
    }
    for (int e = t; e < 1600; e += 400) {
        int m = e / 40, hh = e % 40;
        float2 w = *(const float2*)&g_Wh[(m * H_ + h0 + hh) * 2];
        *(float4*)&w4[(m * 41 + hh) * 4] = make_float4(w.x, w.x, w.y, w.y);
    }
    __syncthreads();

    int hh = t / 10;
    int kxp = t % 10;     // kx pair: {2*kxp, 2*kxp+1}
    u64 REc = 0ULL, REs = 0ULL, IM = 0ULL;
#pragma unroll 8
    for (int m = 0; m < 40; m++) {
        ulonglong2 wq = *(const ulonglong2*)&w4[(m * 41 + hh) * 4];  // {c,c},{s,s}
        u64 AR = *(const u64*)&s3re[m * 20 + kxp * 2];
        u64 AI = *(const u64*)&s3im[m * 20 + kxp * 2];
        fma2(REc, AR, wq.x);   // + ar*c
        fma2(REs, AI, wq.y);   // + ai*s  (re = REc - REs)
        fma2(IM,  AR, wq.y);   // + ar*s
        fma2(IM,  AI, wq.x);   // + ai*c
    }
    float rc0, rc1, rs0, rs1, i0, i1;
    unpack2(REc, rc0, rc1);
    unpack2(REs, rs0, rs1);
    unpack2(IM, i0, i1);
    float sc0 = ((kxp == 0) ? 1.0f : 2.0f) * (1.0f / 250000.0f);
    float sc1 = 2.0f * (1.0f / 250000.0f);
    float4 v = make_float4((rc0 - rs0) * sc0, i0 * sc0, (rc1 - rs1) * sc1, i1 * sc1);
    *(float4*)&T[((size_t)bc * H_ + h0 + hh) * 40 + kxp * 4] = v;
}

// ---------------- stage 2 inverse + pointwise conv (augmented GEMM, 4w-vec x 8o FFMA2) ----
__global__ void __launch_bounds__(160) k_iw_conv(const float* __restrict__ T,
                                                 const float* __restrict__ Ain,
                                                 const float* __restrict__ cw,
                                                 const float* __restrict__ cb, int l,
                                                 float* __restrict__ Aout, int do_gelu) {
    __shared__ float R[72][160];
    __shared__ float Lh[72][32];
    int tid = threadIdx.x;
    int wt = blockIdx.x, h = blockIdx.y, b = blockIdx.z;
    int w0 = wt * 160;

    for (int e = tid; e < 40 * 40; e += 160) {
        int kz = e / 40, w4i = e % 40;
        *(float4*)&R[kz][w4i * 4] = *(const float4*)&g_Gi[kz * W_ + w0 + w4i * 4];
    }
    for (int e = tid; e < 32 * 40; e += 160) {
        int i = e / 40, w4i = e % 40;
        *(float4*)&R[40 + i][w4i * 4] =
            *(const float4*)&Ain[((size_t)(b * C_ + i)) * NPIX + h * W_ + w0 + w4i * 4];
    }
    for (int e = tid; e < 32 * 10; e += 160) {          // T: float4 loads, scattered STS
        int o = e / 10, kz4 = e % 10;
        float4 v = *(const float4*)&T[((size_t)(b * C_ + o) * H_ + h) * 40 + kz4 * 4];
        Lh[kz4 * 4][o] = v.x;
        Lh[kz4 * 4 + 1][o] = v.y;
        Lh[kz4 * 4 + 2][o] = v.z;
        Lh[kz4 * 4 + 3][o] = v.w;
    }
    for (int e = tid; e < 32 * 8; e += 160) {           // cw: float4 loads
        int o = e / 8, i4 = e % 8;
        float4 v = *(const float4*)&cw[l * 1024 + o * 32 + i4 * 4];
        Lh[40 + i4 * 4][o] = v.x;
        Lh[40 + i4 * 4 + 1][o] = v.y;
        Lh[40 + i4 * 4 + 2][o] = v.z;
        Lh[40 + i4 * 4 + 3][o] = v.w;
    }
    __syncthreads();

    int og = tid / 40;
    int wl = tid % 40;
    int o0 = og * 8;
    u64 aP[4][4];
#pragma unroll
    for (int p = 0; p < 4; p++) {
        u64 bias = pack2(cb[l * 32 + o0 + 2 * p], cb[l * 32 + o0 + 2 * p + 1]);
#pragma unroll
        for (int q = 0; q < 4; q++) aP[q][p] = bias;
    }

#pragma unroll 4
    for (int k = 0; k < 72; k++) {
        float4 rv = *(const float4*)&R[k][wl * 4];
        u64 r2[4];
        r2[0] = pack2(rv.x, rv.x);
        r2[1] = pack2(rv.y, rv.y);
        r2[2] = pack2(rv.z, rv.z);
        r2[3] = pack2(rv.w, rv.w);
        ulonglong2 lq0 = *(const ulonglong2*)&Lh[k][o0];
        ulonglong2 lq1 = *(const ulonglong2*)&Lh[k][o0 + 4];
#pragma unroll
        for (int q = 0; q < 4; q++) {
            fma2(aP[q][0], r2[q], lq0.x);
            fma2(aP[q][1], r2[q], lq0.y);
            fma2(aP[q][2], r2[q], lq1.x);
            fma2(aP[q][3], r2[q], lq1.y);
        }
    }
#pragma unroll
    for (int p = 0; p < 4; p++) {
        float rowA[4], rowB[4];
#pragma unroll
        for (int q = 0; q < 4; q++) {
            unpack2(aP[q][p], rowA[q], rowB[q]);
            if (do_gelu) { rowA[q] = gelu_f(rowA[q]); rowB[q] = gelu_f(rowB[q]); }
        }
        size_t baseA = ((size_t)(b * C_ + o0 + 2 * p)) * NPIX + h * W_ + w0 + wl * 4;
        size_t baseB = ((size_t)(b * C_ + o0 + 2 * p + 1)) * NPIX + h * W_ + w0 + wl * 4;
        *(float4*)&Aout[baseA] = *(float4*)&rowA[0];
        *(float4*)&Aout[baseB] = *(float4*)&rowB[0];
    }
}

// ---------------- final: proj MLP + 3x3 mask conv + combine (2-pixel tile) ----------------
__global__ void __launch_bounds__(256) k_final(
        const float* __restrict__ A, const float* __restrict__ input,
        const float* __restrict__ src,
        const float* __restrict__ pw1, const float* __restrict__ pb1,
        const float* __restrict__ pw2, const float* __restrict__ pb2,
        const float* __restrict__ mw, const float* __restrict__ mb,
        float* __restrict__ out) {
    __shared__ __align__(16) float spw1[32][16];
    __shared__ __align__(16) float spb1[16];
    __shared__ float spw2[32];
    __shared__ float spb2v[2];
    __shared__ float smw[9];
    __shared__ float smb0;
    int tid = threadIdx.x;
    for (int e = tid; e < 512; e += 256) (&spw1[0][0])[e] = pw1[e];
    if (tid < 16) spb1[tid] = pb1[tid];
    if (tid >= 16 && tid < 48) spw2[tid - 16] = pw2[tid - 16];
    if (tid >= 48 && tid < 50) spb2v[tid - 48] = pb2[tid - 48];
    if (tid >= 64 && tid < 73) smw[tid - 64] = mw[tid - 64];
    if (tid == 73) smb0 = mb[0];
    __syncthreads();

    int p0 = (blockIdx.x * 256 + tid) * 2;
    int w = p0 % W_;
    int h = (p0 / W_) % H_;
    int b = p0 / NPIX;
    int hw = h * W_ + w;

    const float* ap = A + (size_t)b * C_ * NPIX + hw;
    u64 hp0[8], hp1[8];
#pragma unroll
    for (int jp = 0; jp < 8; jp++) {
        u64 bp = *(const u64*)&spb1[jp * 2];
        hp0[jp] = bp; hp1[jp] = bp;
    }
#pragma unroll 8
    for (int i = 0; i < 32; i++) {
        float2 av = *(const float2*)&ap[(size_t)i * NPIX];
        u64 a0 = pack2(av.x, av.x);
        u64 a1 = pack2(av.y, av.y);
#pragma unroll
        for (int jp = 0; jp < 8; jp++) {
            u64 wp = *(const u64*)&spw1[i][jp * 2];
            fma2(hp0[jp], a0, wp);
            fma2(hp1[jp], a1, wp);
        }
    }
    float p00 = spb2v[0], p01 = spb2v[1];
    float p10 = spb2v[0], p11 = spb2v[1];
#pragma unroll
    for (int jp = 0; jp < 8; jp++) {
        float a, bb;
        unpack2(hp0[jp], a, bb);
        float g0 = gelu_f(a), g1 = gelu_f(bb);
        p00 += g0 * spw2[(jp * 2) * 2]     + g1 * spw2[(jp * 2 + 1) * 2];
        p01 += g0 * spw2[(jp * 2) * 2 + 1] + g1 * spw2[(jp * 2 + 1) * 2 + 1];
        unpack2(hp1[jp], a, bb);
        g0 = gelu_f(a); g1 = gelu_f(bb);
        p10 += g0 * spw2[(jp * 2) * 2]     + g1 * spw2[(jp * 2 + 1) * 2];
        p11 += g0 * spw2[(jp * 2) * 2 + 1] + g1 * spw2[(jp * 2 + 1) * 2 + 1];
    }

    float m0 = smb0, m1 = smb0;
#pragma unroll
    for (int dy = -1; dy <= 1; dy++) {
        int hh = h + dy;
        if (hh < 0 || hh >= H_) continue;
        const float* row = input + ((size_t)(b * H_ + hh)) * W_;
#pragma unroll
        for (int dx = -1; dx <= 2; dx++) {
            int ww = w + dx;
            if (ww < 0 || ww >= W_) continue;
            float v = row[ww];
            if (dx <= 1) m0 += v * smw[(dy + 1) * 3 + (dx + 1)];
            if (dx >= 0) m1 += v * smw[(dy + 1) * 3 + dx];
        }
    }
    const float* sp = src + (size_t)p0 * 3;
    float2 s01 = *(const float2*)sp;
    float2 s23 = *(const float2*)(sp + 2);
    float2 s45 = *(const float2*)(sp + 4);
    float4 ov;
    ov.x = s01.y * m0 + p00;
    ov.y = s23.x * m0 + p01;
    ov.z = s45.x * m1 + p10;
    ov.w = s45.y * m1 + p11;
    *(float4*)&out[(size_t)p0 * 2] = ov;
}

// ---------------- launcher ----------------
extern "C" void kernel_launch(void* const* d_in, const int* in_sizes, int n_in,
                              void* d_out, int out_size) {
    const float* input = (const float*)d_in[0];
    const float* src   = (const float*)d_in[1];
    const float* iw1   = (const float*)d_in[2];
    const float* ib1   = (const float*)d_in[3];
    const float* iw2   = (const float*)d_in[4];
    const float* ib2   = (const float*)d_in[5];
    const float* ew1   = (const float*)d_in[6];
    const float* eb1   = (const float*)d_in[7];
    const float* ew2   = (const float*)d_in[8];
    const float* eb2   = (const float*)d_in[9];
    const float* fw1   = (const float*)d_in[10];
    const float* fw2   = (const float*)d_in[11];
    const float* cw    = (const float*)d_in[12];
    const float* cb    = (const float*)d_in[13];
    const float* pw1   = (const float*)d_in[14];
    const float* pb1   = (const float*)d_in[15];
    const float* pw2   = (const float*)d_in[16];
    const float* pb2   = (const float*)d_in[17];
    const float* mw    = (const float*)d_in[18];
    const float* mb    = (const float*)d_in[19];

    float *A, *Bp, *E, *S1, *S2p, *S2, *S3, *T;
    cudaGetSymbolAddress((void**)&A,   g_bufA);
    cudaGetSymbolAddress((void**)&Bp,  g_bufB);
    cudaGetSymbolAddress((void**)&E,   g_E);
    cudaGetSymbolAddress((void**)&S1,  g_S1);
    cudaGetSymbolAddress((void**)&S2p, g_S2p);
    cudaGetSymbolAddress((void**)&S2,  g_S2);
    cudaGetSymbolAddress((void**)&S3,  g_S3);
    cudaGetSymbolAddress((void**)&T,   g_T);

    k_tables<<<75, 256>>>();
    k_encode<<<Bb_ * NPIX / 512, 256>>>(input, src, iw1, ib1, iw2, ib2,
                                        ew1, eb1, ew2, eb2, A, E);
    for (int l = 0; l < 4; l++) {
        float* Ain  = (l & 1) ? Bp : A;
        float* Aout = (l & 1) ? A  : Bp;
        dim3 gfw(NROWS / FW_BM, WSPLIT);
        k_fft_w<<<gfw, 160>>>(Ain, E, S1);
        dim3 gfh(BC, KSPLIT);
        k_fft_h<<<gfh, 400>>>(S1, S2p);
        k_red<<<(BC * 1600 / 4 + 255) / 256, 256>>>(S2p, S2);
        k_mix<<<(Bb_ * C_ * NM * WN_ * 2 + 255) / 256, 256>>>(S2, fw1, fw2, l, S3);
        dim3 gih(BC, KSPLIT);
        k_ifft_h<<<gih, 400>>>(S3, T);
        dim3 g(W_ / 160, H_, Bb_);
        k_iw_conv<<<g, 160>>>(T, Ain, cw, cb, l, Aout, (l < 3) ? 1 : 0);
    }
    k_final<<<Bb_ * NPIX / 512, 256>>>(A, input, src, pw1, pb1, pw2, pb2,
                                       mw, mb, (float*)d_out);
}

// round 17
// speedup vs baseline: 1.0924x; 1.0924x over previous
#include <cuda_runtime.h>
#include <cuda_bf16.h>
#include <math.h>

#define Bb_ 2
#define H_ 480
#define W_ 480
#define C_ 32
#define BC 64
#define HP 500
#define WN_ 20
#define NM 40           // 40 ky modes (20 low + 20 high)
#define NPIX (H_*W_)    // 230400
#define NROWS (BC*H_)   // 30720
#define KSPLIT 12       // h-split (480 = 12*40)
#define NPART 12

typedef unsigned long long u64;

__device__ __forceinline__ u64 pack2(float lo, float hi) {
    u64 r; asm("mov.b64 %0, {%1, %2};" : "=l"(r) : "f"(lo), "f"(hi)); return r;
}
__device__ __forceinline__ void unpack2(u64 v, float& lo, float& hi) {
    asm("mov.b64 {%0, %1}, %2;" : "=f"(lo), "=f"(hi) : "l"(v));
}
__device__ __forceinline__ void fma2(u64& d, u64 a, u64 b) {
    asm("fma.rn.f32x2 %0, %1, %2, %0;" : "+l"(d) : "l"(a), "l"(b));
}

// ---------------- device scratch (static; no allocations) ----------------
__device__ float g_bufA[BC*NPIX];         // 59 MB
__device__ float g_bufB[BC*NPIX];         // 59 MB
__device__ float g_E[BC*NPIX];            // 59 MB
__device__ float g_S1[2*NROWS*40];        // w-split partials: [half][row][kz]
__device__ float g_S2p[NPART*BC*1600];    // h-split partials: [sp][bc][1600]
__device__ float g_S2[BC*1600];           // summed: [bc][m][kx][z]
__device__ float g_S3[BC*NM*WN_*2];       // [b][o][m][kx][z]
__device__ float g_T[NROWS*40];           // [bc*480+h][kz] (scaled)
__device__ float g_Wt[W_*40];             // fwd w-twiddle: [w][2kx+z] (z=1 -> -sin)
__device__ float g_Wh[NM*H_*2];           // ky twiddle: [m][h]{cos,sin}
__device__ float g_Gi[40*W_];             // inv w-twiddle rows: [2kx+z][w] (z=1 -> -sin)

__device__ __forceinline__ float gelu_f(float x) {
    return 0.5f * x * (1.0f + erff(x * 0.70710678118654752f));
}

// ---------------- trig tables ----------------
__global__ void k_tables() {
    int t = blockIdx.x * blockDim.x + threadIdx.x;
    if (t < W_ * 40) {
        int c = t % 40, w = t / 40;
        int kx = c >> 1;
        int idx = (kx * w) % 500;
        float s, cc;
        sincospif(2.0f * (float)idx / 500.0f, &s, &cc);
        g_Wt[t] = (c & 1) ? -s : cc;
    }
    if (t < NM * H_) {
        int h = t % H_, m = t / H_;
        int ky = (m < 20) ? m : (460 + m);
        int idx = (ky * h) % 500;
        float s, cc;
        sincospif(2.0f * (float)idx / 500.0f, &s, &cc);
        g_Wh[t * 2] = cc;
        g_Wh[t * 2 + 1] = s;
    }
    if (t < 40 * W_) {
        int w = t % W_, kz = t / W_;
        int kx = kz >> 1;
        int idx = (kx * w) % 500;
        float s, cc;
        sincospif(2.0f * (float)idx / 500.0f, &s, &cc);
        g_Gi[t] = (kz & 1) ? -s : cc;
    }
}

// ---------------- encoder: two tiny MLPs -> A0, E (2-pixel tile, shared weights) --------
__global__ void __launch_bounds__(256) k_encode(
        const float* __restrict__ input, const float* __restrict__ src,
        const float* __restrict__ iw1, const float* __restrict__ ib1,
        const float* __restrict__ iw2, const float* __restrict__ ib2,
        const float* __restrict__ ew1, const float* __restrict__ eb1,
        const float* __restrict__ ew2, const float* __restrict__ eb2,
        float* __restrict__ A, float* __restrict__ E) {
    __shared__ __align__(16) float siw1[5][16];
    __shared__ __align__(16) float sib1[16];
    __shared__ __align__(16) float siw2[16][32];
    __shared__ __align__(16) float sib2[32];
    __shared__ __align__(16) float sew1[3][16];
    __shared__ __align__(16) float seb1[16];
    __shared__ __align__(16) float sew2[16][32];
    __shared__ __align__(16) float seb2[32];
    int tid = threadIdx.x;
    if (tid < 80) (&siw1[0][0])[tid] = iw1[tid];
    if (tid >= 80 && tid < 96) sib1[tid - 80] = ib1[tid - 80];
    if (tid >= 96 && tid < 144) (&sew1[0][0])[tid - 96] = ew1[tid - 96];
    if (tid >= 144 && tid < 160) seb1[tid - 144] = eb1[tid - 144];
    if (tid >= 160 && tid < 192) sib2[tid - 160] = ib2[tid - 160];
    if (tid >= 192 && tid < 224) seb2[tid - 192] = eb2[tid - 192];
    for (int e = tid; e < 512; e += 256) {
        (&siw2[0][0])[e] = iw2[e];
        (&sew2[0][0])[e] = ew2[e];
    }
    __syncthreads();

    int p0 = (blockIdx.x * 256 + tid) * 2;
    int w = p0 % W_;
    int h = (p0 / W_) % H_;
    int b = p0 / NPIX;
    int hw = h * W_ + w;
    float gx = (float)h * (1.0f / 479.0f);
    float gy0 = (float)w * (1.0f / 479.0f);
    float gy1 = (float)(w + 1) * (1.0f / 479.0f);

    const float* sp = src + (size_t)p0 * 3;
    float2 s01 = *(const float2*)sp;
    float2 s23 = *(const float2*)(sp + 2);
    float2 s45 = *(const float2*)(sp + 4);
    float xin0[5] = { s01.x, s01.y, s23.x, gx, gy0 };
    float xin1[5] = { s23.y, s45.x, s45.y, gx, gy1 };
    float2 iv = *(const float2*)&input[(size_t)p0];
    float xe0[3] = { iv.x, gx, gy0 };
    float xe1[3] = { iv.y, gx, gy1 };

    // ---- in-MLP ----
    {
        u64 hp0[8], hp1[8];
#pragma unroll
        for (int jp = 0; jp < 8; jp++) {
            u64 bp = *(const u64*)&sib1[jp * 2];
            hp0[jp] = bp; hp1[jp] = bp;
        }
#pragma unroll
        for (int f = 0; f < 5; f++) {
            u64 x0 = pack2(xin0[f], xin0[f]);
            u64 x1 = pack2(xin1[f], xin1[f]);
#pragma unroll
            for (int jp = 0; jp < 8; jp++) {
                u64 wp = *(const u64*)&siw1[f][jp * 2];
                fma2(hp0[jp], x0, wp);
                fma2(hp1[jp], x1, wp);
            }
        }
        float hid0[16], hid1[16];
#pragma unroll
        for (int jp = 0; jp < 8; jp++) {
            float a, bb;
            unpack2(hp0[jp], a, bb);
            hid0[jp * 2] = gelu_f(a); hid0[jp * 2 + 1] = gelu_f(bb);
            unpack2(hp1[jp], a, bb);
            hid1[jp * 2] = gelu_f(a); hid1[jp * 2 + 1] = gelu_f(bb);
        }
#pragma unroll
        for (int ch = 0; ch < 2; ch++) {
            int c0 = ch * 16;
            u64 acc0[8], acc1[8];
#pragma unroll
            for (int cp = 0; cp < 8; cp++) {
                u64 bp = *(const u64*)&sib2[c0 + cp * 2];
                acc0[cp] = bp; acc1[cp] = bp;
            }
#pragma unroll
            for (int j = 0; j < 16; j++) {
                u64 h0 = pack2(hid0[j], hid0[j]);
                u64 h1 = pack2(hid1[j], hid1[j]);
#pragma unroll
                for (int cp = 0; cp < 8; cp++) {
                    u64 wp = *(const u64*)&siw2[j][c0 + cp * 2];
                    fma2(acc0[cp], h0, wp);
                    fma2(acc1[cp], h1, wp);
                }
            }
#pragma unroll
            for (int cp = 0; cp < 8; cp++) {
                float a0lo, a0hi, a1lo, a1hi;
                unpack2(acc0[cp], a0lo, a0hi);
                unpack2(acc1[cp], a1lo, a1hi);
                int clo = c0 + cp * 2;
                *(float2*)&A[((size_t)(b * C_ + clo)) * NPIX + hw] = make_float2(a0lo, a1lo);
                *(float2*)&A[((size_t)(b * C_ + clo + 1)) * NPIX + hw] = make_float2(a0hi, a1hi);
            }
        }
    }
    // ---- eps-MLP ----
    {
        u64 hp0[8], hp1[8];
#pragma unroll
        for (int jp = 0; jp < 8; jp++) {
            u64 bp = *(const u64*)&seb1[jp * 2];
            hp0[jp] = bp; hp1[jp] = bp;
        }
#pragma unroll
        for (int f = 0; f < 3; f++) {
            u64 x0 = pack2(xe0[f], xe0[f]);
            u64 x1 = pack2(xe1[f], xe1[f]);
#pragma unroll
            for (int jp = 0; jp < 8; jp++) {
                u64 wp = *(const u64*)&sew1[f][jp * 2];
                fma2(hp0[jp], x0, wp);
                fma2(hp1[jp], x1, wp);
            }
        }
        float hid0[16], hid1[16];
#pragma unroll
        for (int jp = 0; jp < 8; jp++) {
            float a, bb;
            unpack2(hp0[jp], a, bb);
            hid0[jp * 2] = gelu_f(a); hid0[jp * 2 + 1] = gelu_f(bb);
            unpack2(hp1[jp], a, bb);
            hid1[jp * 2] = gelu_f(a); hid1[jp * 2 + 1] = gelu_f(bb);
        }
#pragma unroll
        for (int ch = 0; ch < 2; ch++) {
            int c0 = ch * 16;
            u64 acc0[8], acc1[8];
#pragma unroll
            for (int cp = 0; cp < 8; cp++) {
                u64 bp = *(const u64*)&seb2[c0 + cp * 2];
                acc0[cp] = bp; acc1[cp] = bp;
            }
#pragma unroll
            for (int j = 0; j < 16; j++) {
                u64 h0 = pack2(hid0[j], hid0[j]);
                u64 h1 = pack2(hid1[j], hid1[j]);
#pragma unroll
                for (int cp = 0; cp < 8; cp++) {
                    u64 wp = *(const u64*)&sew2[j][c0 + cp * 2];
                    fma2(acc0[cp], h0, wp);
                    fma2(acc1[cp], h1, wp);
                }
            }
#pragma unroll
            for (int cp = 0; cp < 8; cp++) {
                float a0lo, a0hi, a1lo, a1hi;
                unpack2(acc0[cp], a0lo, a0hi);
                unpack2(acc1[cp], a1lo, a1hi);
                int clo = c0 + cp * 2;
                *(float2*)&E[((size_t)(b * C_ + clo)) * NPIX + hw] = make_float2(a0lo, a1lo);
                *(float2*)&E[((size_t)(b * C_ + clo + 1)) * NPIX + hw] = make_float2(a0hi, a1hi);
            }
        }
    }
}

// ---------------- stage 1 forward: per-row w-DFT, 2-way K-split, FFMA2, f4 staging -----
#define FW_BM 96
#define FW_BK 48
__global__ void __launch_bounds__(160) k_fft_w(const float* __restrict__ A,
                                               const float* __restrict__ E,
                                               float* __restrict__ S1p) {
    __shared__ float sp[FW_BM][52];
    __shared__ float st[FW_BK][40];
    int tid = threadIdx.x;
    int half = blockIdx.y;
    int row0 = blockIdx.x * FW_BM;
    int bc = row0 / H_;
    int hbase = row0 % H_;
    const float* abase = A + (size_t)bc * NPIX + hbase * W_ + half * 240;
    const float* ebase = E + (size_t)bc * NPIX + hbase * W_ + half * 240;
    int tx = tid % 10;
    int ty = tid / 10;
    u64 accP[6][2];
#pragma unroll
    for (int i = 0; i < 6; i++) { accP[i][0] = 0ULL; accP[i][1] = 0ULL; }

    for (int k0 = 0; k0 < 240; k0 += FW_BK) {
        for (int e = tid; e < FW_BM * (FW_BK / 4); e += 160) {
            int r = e / 12, k4 = e % 12;
            float4 a = *(const float4*)&abase[r * W_ + k0 + k4 * 4];
            float4 ev = *(const float4*)&ebase[r * W_ + k0 + k4 * 4];
            float4 pv = make_float4(a.x * ev.x, a.y * ev.y, a.z * ev.z, a.w * ev.w);
            *(float4*)&sp[r][k4 * 4] = pv;
        }
        {
            const float* wt = g_Wt + (half * 240 + k0) * 40;
            for (int e = tid; e < FW_BK * 10; e += 160) {
                int row = e / 10, c4 = e % 10;
                *(float4*)&st[row][c4 * 4] = *(const float4*)&wt[row * 40 + c4 * 4];
            }
        }
        __syncthreads();
#pragma unroll
        for (int kk = 0; kk < FW_BK; kk += 4) {
            float avf[6][4];
            ulonglong2 bq[4];
#pragma unroll
            for (int i = 0; i < 6; i++)
                *(float4*)avf[i] = *(const float4*)&sp[ty * 6 + i][kk];
#pragma unroll
            for (int t = 0; t < 4; t++)
                bq[t] = *(const ulonglong2*)&st[kk + t][tx * 4];
#pragma unroll
            for (int t = 0; t < 4; t++) {
#pragma unroll
                for (int i = 0; i < 6; i++) {
                    u64 a2 = pack2(avf[i][t], avf[i][t]);
                    fma2(accP[i][0], a2, bq[t].x);
                    fma2(accP[i][1], a2, bq[t].y);
                }
            }
        }
        __syncthreads();
    }
#pragma unroll
    for (int i = 0; i < 6; i++) {
        int r = row0 + ty * 6 + i;
        float4 v;
        unpack2(accP[i][0], v.x, v.y);
        unpack2(accP[i][1], v.z, v.w);
        *(float4*)&S1p[((size_t)half * NROWS + r) * 40 + tx * 4] = v;
    }
}

// ---------------- stage 2 forward: ky-DFT, planar FFMA2, in-block reduction ----------------
// grid (BC, 12); block 400 = 4 subtiles(10h) x 20 m-groups(2) x 5 kx-groups(4)
__global__ void __launch_bounds__(400) k_fft_h(const float* __restrict__ S1p,
                                               float* __restrict__ S2p) {
    __shared__ __align__(16) float pool[1600 + 1600 + 6560];
    float* s1re = pool;             // [40][20]
    float* s1im = pool + 1600;      // [40][20]
    float* w4   = pool + 3200;      // [40][41][4] {c,c,s,s}; reused as reduction buf
    int bc = blockIdx.x;
    int spg = blockIdx.y;
    int t = threadIdx.x;
    int h0 = spg * 40;
    const float* base0 = S1p + (size_t)(bc * H_) * 40;
    const float* base1 = S1p + (size_t)(NROWS + bc * H_) * 40;

    for (int e = t; e < 800; e += 400) {
        int hh = e / 20, kx = e % 20;
        float2 a = *(const float2*)&base0[(h0 + hh) * 40 + kx * 2];
        float2 b = *(const float2*)&base1[(h0 + hh) * 40 + kx * 2];
        s1re[hh * 20 + kx] = a.x + b.x;
        s1im[hh * 20 + kx] = a.y + b.y;
    }
    for (int e = t; e < 1600; e += 400) {
        int m = e / 40, hh = e % 40;
        float2 w = *(const float2*)&g_Wh[(m * H_ + h0 + hh) * 2];
        *(float4*)&w4[(m * 41 + hh) * 4] = make_float4(w.x, w.x, w.y, w.y);
    }
    __syncthreads();

    int sub = t / 100;           // 4 subtiles of 10 h
    int r = t % 100;
    int mg = r / 5;              // 20 m-groups of 2
    int kxg = r % 5;             // 5 kx-groups of 4 kx (2 u64 pairs)
    int m0 = mg * 2;
    u64 AR[2][2], AC[2][2], AS[2][2];
#pragma unroll
    for (int mi = 0; mi < 2; mi++)
#pragma unroll
        for (int j = 0; j < 2; j++) { AR[mi][j] = 0ULL; AC[mi][j] = 0ULL; AS[mi][j] = 0ULL; }

#pragma unroll
    for (int hh = 0; hh < 10; hh++) {
        int hl = sub * 10 + hh;
        ulonglong2 REq = *(const ulonglong2*)&s1re[hl * 20 + kxg * 4];
        ulonglong2 IMq = *(const ulonglong2*)&s1im[hl * 20 + kxg * 4];
#pragma unroll
        for (int mi = 0; mi < 2; mi++) {
            ulonglong2 wq = *(const ulonglong2*)&w4[((m0 + mi) * 41 + hl) * 4]; // {c,c},{s,s}
            fma2(AR[mi][0], REq.x, wq.x);
            fma2(AR[mi][1], REq.y, wq.x);
            fma2(AR[mi][0], IMq.x, wq.y);
            fma2(AR[mi][1], IMq.y, wq.y);
            fma2(AC[mi][0], IMq.x, wq.x);
            fma2(AC[mi][1], IMq.y, wq.x);
            fma2(AS[mi][0], REq.x, wq.y);
            fma2(AS[mi][1], REq.y, wq.y);
        }
    }
    __syncthreads();   // all w4 reads done; safe to overwrite with partials

#pragma unroll
    for (int mi = 0; mi < 2; mi++) {
#pragma unroll
        for (int jj = 0; jj < 2; jj++) {
            float ar0, ar1, c0, c1, s0, s1v;
            unpack2(AR[mi][jj], ar0, ar1);
            unpack2(AC[mi][jj], c0, c1);
            unpack2(AS[mi][jj], s0, s1v);
            float4 v = make_float4(ar0, c0 - s0, ar1, c1 - s1v);
            *(float4*)&w4[t * 16 + mi * 8 + jj * 4] = v;
        }
    }
    __syncthreads();

    size_t obase = ((size_t)spg * BC + bc) * 1600;
#pragma unroll
    for (int gofs = 0; gofs < 4; gofs++) {
        int g = t + gofs * 400;
        int m = g / 40;
        int rem = g % 40;
        int kx2 = rem / 4;
        int q = rem % 4;
        int rr = (m / 2) * 5 + kx2 / 2;
        int j = (m % 2) * 8 + (kx2 % 2) * 4 + q;
        float a = 0.f;
#pragma unroll
        for (int sb = 0; sb < 4; sb++)
            a += w4[(sb * 100 + rr) * 16 + j];
        S2p[obase + g] = a;
    }
}

// ---------------- reduce split partials (float4) ----------------
__global__ void k_red(const float* __restrict__ P, float* __restrict__ S) {
    int t = blockIdx.x * blockDim.x + threadIdx.x;
    if (t >= BC * 1600 / 4) return;
    float4 a = make_float4(0.f, 0.f, 0.f, 0.f);
#pragma unroll
    for (int p = 0; p < NPART; p++) {
        float4 v = *(const float4*)&P[(size_t)p * BC * 1600 + t * 4];
        a.x += v.x; a.y += v.y; a.z += v.z; a.w += v.w;
    }
    *(float4*)&S[t * 4] = a;
}

// ---------------- mode mixing (z-pair vectorized) ----------------
__global__ void k_mix(const float* __restrict__ S2, const float* __restrict__ fw1,
                      const float* __restrict__ fw2, int l, float* __restrict__ S3) {
    int t = blockIdx.x * blockDim.x + threadIdx.x;
    if (t >= Bb_ * C_ * NM * WN_) return;
    int kx = t % WN_;
    int m = (t / WN_) % NM;
    int o = (t / (WN_ * NM)) % C_;
    int b = t / (WN_ * NM * C_);
    const float* wb;
    if (m < 20) wb = fw1 + l * 819200 + o * 800 + m * 40 + kx * 2;
    else        wb = fw2 + l * 819200 + o * 800 + (m - 20) * 40 + kx * 2;
    const float* s2 = S2 + (b * C_) * 1600 + m * (WN_ * 2) + kx * 2;
    float2 acc = make_float2(0.f, 0.f);
#pragma unroll 8
    for (int i = 0; i < C_; i++) {
        float2 sv = *(const float2*)&s2[i * 1600];
        float2 wv = *(const float2*)&wb[i * 25600];
        acc.x += sv.x * wv.x;
        acc.y += sv.y * wv.y;
    }
    *(float2*)&S3[((b * C_ + o) * NM + m) * (WN_ * 2) + kx * 2] = acc;
}

// ---------------- stage 1 inverse: ky synthesis, planar FFMA2 shared tiles ----------------
// grid (BC, 12); block 400 = 40 h x 10 kx-pairs
__global__ void __launch_bounds__(400) k_ifft_h(const float* __restrict__ S3,
                                                float* __restrict__ T) {
    __shared__ __align__(16) float pool[1600 + 1600 + 6560];
    float* s3re = pool;             // [40 m][20 kx]
    float* s3im = pool + 1600;      // [40 m][20 kx]
    float* w4   = pool + 3200;      // [40 m][41 hh][4] {c,c,s,s}
    int bc = blockIdx.x;
    int spg = blockIdx.y;
    int t = threadIdx.x;
    int h0 = spg * 40;
    const float* s3 = S3 + (size_t)bc * 1600;

    for (int e = t; e < 800; e += 400) {
        int m = e / 20, kx = e % 20;
        float2 a = *(const float2*)&s3[m * 40 + kx * 2];
        s3re[m * 20 + kx] = a.x;
        s3im[m * 20 + kx] = a.y;
    }
    for (int e = t; e < 1600; e += 400) {
        int m = e / 40, hh = e % 40;
        float2 w = *(const float2*)&g_Wh[(m * H_ + h0 + hh) * 2];
        *(float4*)&w4[(m * 41 + hh) * 4] = make_float4(w.x, w.x, w.y, w.y);
    }
    __syncthreads();

    int hh = t / 10;
    int kxp = t % 10;     // kx pair: {2*kxp, 2*kxp+1}
    u64 REc = 0ULL, REs = 0ULL, IM = 0ULL;
#pragma unroll 8
    for (int m = 0; m < 40; m++) {
        ulonglong2 wq = *(const ulonglong2*)&w4[(m * 41 + hh) * 4];  // {c,c},{s,s}
        u64 AR = *(const u64*)&s3re[m * 20 + kxp * 2];
        u64 AI = *(const u64*)&s3im[m * 20 + kxp * 2];
        fma2(REc, AR, wq.x);   // + ar*c
        fma2(REs, AI, wq.y);   // + ai*s  (re = REc - REs)
        fma2(IM,  AR, wq.y);   // + ar*s
        fma2(IM,  AI, wq.x);   // + ai*c
    }
    float rc0, rc1, rs0, rs1, i0, i1;
    unpack2(REc, rc0, rc1);
    unpack2(REs, rs0, rs1);
    unpack2(IM, i0, i1);
    float sc0 = ((kxp == 0) ? 1.0f : 2.0f) * (1.0f / 250000.0f);
    float sc1 = 2.0f * (1.0f / 250000.0f);
    float4 v = make_float4((rc0 - rs0) * sc0, i0 * sc0, (rc1 - rs1) * sc1, i1 * sc1);
    *(float4*)&T[((size_t)bc * H_ + h0 + hh) * 40 + kxp * 4] = v;
}

// ---------------- stage 2 inverse + pointwise conv (augmented GEMM, 4w-vec x 8o FFMA2) ----
__global__ void __launch_bounds__(160) k_iw_conv(const float* __restrict__ T,
                                                 const float* __restrict__ Ain,
                                                 const float* __restrict__ cw,
                                                 const float* __restrict__ cb, int l,
                                                 float* __restrict__ Aout, int do_gelu) {
    __shared__ float R[72][160];
    __shared__ float Lh[72][32];
    int tid = threadIdx.x;
    int wt = blockIdx.x, h = blockIdx.y, b = blockIdx.z;
    int w0 = wt * 160;

    for (int e = tid; e < 40 * 40; e += 160) {
        int kz = e / 40, w4i = e % 40;
        *(float4*)&R[kz][w4i * 4] = *(const float4*)&g_Gi[kz * W_ + w0 + w4i * 4];
    }
    for (int e = tid; e < 32 * 40; e += 160) {
        int i = e / 40, w4i = e % 40;
        *(float4*)&R[40 + i][w4i * 4] =
            *(const float4*)&Ain[((size_t)(b * C_ + i)) * NPIX + h * W_ + w0 + w4i * 4];
    }
    for (int e = tid; e < 32 * 10; e += 160) {          // T: float4 loads, scattered STS
        int o = e / 10, kz4 = e % 10;
        float4 v = *(const float4*)&T[((size_t)(b * C_ + o) * H_ + h) * 40 + kz4 * 4];
        Lh[kz4 * 4][o] = v.x;
        Lh[kz4 * 4 + 1][o] = v.y;
        Lh[kz4 * 4 + 2][o] = v.z;
        Lh[kz4 * 4 + 3][o] = v.w;
    }
    for (int e = tid; e < 32 * 8; e += 160) {           // cw: float4 loads
        int o = e / 8, i4 = e % 8;
        float4 v = *(const float4*)&cw[l * 1024 + o * 32 + i4 * 4];
        Lh[40 + i4 * 4][o] = v.x;
        Lh[40 + i4 * 4 + 1][o] = v.y;
        Lh[40 + i4 * 4 + 2][o] = v.z;
        Lh[40 + i4 * 4 + 3][o] = v.w;
    }
    __syncthreads();

    int og = tid / 40;
    int wl = tid % 40;
    int o0 = og * 8;
    u64 aP[4][4];
#pragma unroll
    for (int p = 0; p < 4; p++) {
        u64 bias = pack2(cb[l * 32 + o0 + 2 * p], cb[l * 32 + o0 + 2 * p + 1]);
#pragma unroll
        for (int q = 0; q < 4; q++) aP[q][p] = bias;
    }

#pragma unroll 4
    for (int k = 0; k < 72; k++) {
        float4 rv = *(const float4*)&R[k][wl * 4];
        u64 r2[4];
        r2[0] = pack2(rv.x, rv.x);
        r2[1] = pack2(rv.y, rv.y);
        r2[2] = pack2(rv.z, rv.z);
        r2[3] = pack2(rv.w, rv.w);
        ulonglong2 lq0 = *(const ulonglong2*)&Lh[k][o0];
        ulonglong2 lq1 = *(const ulonglong2*)&Lh[k][o0 + 4];
#pragma unroll
        for (int q = 0; q < 4; q++) {
            fma2(aP[q][0], r2[q], lq0.x);
            fma2(aP[q][1], r2[q], lq0.y);
            fma2(aP[q][2], r2[q], lq1.x);
            fma2(aP[q][3], r2[q], lq1.y);
        }
    }
#pragma unroll
    for (int p = 0; p < 4; p++) {
        float rowA[4], rowB[4];
#pragma unroll
        for (int q = 0; q < 4; q++) {
            unpack2(aP[q][p], rowA[q], rowB[q]);
            if (do_gelu) { rowA[q] = gelu_f(rowA[q]); rowB[q] = gelu_f(rowB[q]); }
        }
        size_t baseA = ((size_t)(b * C_ + o0 + 2 * p)) * NPIX + h * W_ + w0 + wl * 4;
        size_t baseB = ((size_t)(b * C_ + o0 + 2 * p + 1)) * NPIX + h * W_ + w0 + wl * 4;
        *(float4*)&Aout[baseA] = *(float4*)&rowA[0];
        *(float4*)&Aout[baseB] = *(float4*)&rowB[0];
    }
}

// ---------------- final: proj MLP + 3x3 mask conv + combine (2-pixel tile) ----------------
__global__ void __launch_bounds__(256) k_final(
        const float* __restrict__ A, const float* __restrict__ input,
        const float* __restrict__ src,
        const float* __restrict__ pw1, const float* __restrict__ pb1,
        const float* __restrict__ pw2, const float* __restrict__ pb2,
        const float* __restrict__ mw, const float* __restrict__ mb,
        float* __restrict__ out) {
    __shared__ __align__(16) float spw1[32][16];
    __shared__ __align__(16) float spb1[16];
    __shared__ float spw2[32];
    __shared__ float spb2v[2];
    __shared__ float smw[9];
    __shared__ float smb0;
    int tid = threadIdx.x;
    for (int e = tid; e < 512; e += 256) (&spw1[0][0])[e] = pw1[e];
    if (tid < 16) spb1[tid] = pb1[tid];
    if (tid >= 16 && tid < 48) spw2[tid - 16] = pw2[tid - 16];
    if (tid >= 48 && tid < 50) spb2v[tid - 48] = pb2[tid - 48];
    if (tid >= 64 && tid < 73) smw[tid - 64] = mw[tid - 64];
    if (tid == 73) smb0 = mb[0];
    __syncthreads();

    int p0 = (blockIdx.x * 256 + tid) * 2;
    int w = p0 % W_;
    int h = (p0 / W_) % H_;
    int b = p0 / NPIX;
    int hw = h * W_ + w;

    const float* ap = A + (size_t)b * C_ * NPIX + hw;
    u64 hp0[8], hp1[8];
#pragma unroll
    for (int jp = 0; jp < 8; jp++) {
        u64 bp = *(const u64*)&spb1[jp * 2];
        hp0[jp] = bp; hp1[jp] = bp;
    }
#pragma unroll 8
    for (int i = 0; i < 32; i++) {
        float2 av = *(const float2*)&ap[(size_t)i * NPIX];
        u64 a0 = pack2(av.x, av.x);
        u64 a1 = pack2(av.y, av.y);
#pragma unroll
        for (int jp = 0; jp < 8; jp++) {
            u64 wp = *(const u64*)&spw1[i][jp * 2];
            fma2(hp0[jp], a0, wp);
            fma2(hp1[jp], a1, wp);
        }
    }
    float p00 = spb2v[0], p01 = spb2v[1];
    float p10 = spb2v[0], p11 = spb2v[1];
#pragma unroll
    for (int jp = 0; jp < 8; jp++) {
        float a, bb;
        unpack2(hp0[jp], a, bb);
        float g0 = gelu_f(a), g1 = gelu_f(bb);
        p00 += g0 * spw2[(jp * 2) * 2]     + g1 * spw2[(jp * 2 + 1) * 2];
        p01 += g0 * spw2[(jp * 2) * 2 + 1] + g1 * spw2[(jp * 2 + 1) * 2 + 1];
        unpack2(hp1[jp], a, bb);
        g0 = gelu_f(a); g1 = gelu_f(bb);
        p10 += g0 * spw2[(jp * 2) * 2]     + g1 * spw2[(jp * 2 + 1) * 2];
        p11 += g0 * spw2[(jp * 2) * 2 + 1] + g1 * spw2[(jp * 2 + 1) * 2 + 1];
    }

    float m0 = smb0, m1 = smb0;
#pragma unroll
    for (int dy = -1; dy <= 1; dy++) {
        int hh = h + dy;
        if (hh < 0 || hh >= H_) continue;
        const float* row = input + ((size_t)(b * H_ + hh)) * W_;
#pragma unroll
        for (int dx = -1; dx <= 2; dx++) {
            int ww = w + dx;
            if (ww < 0 || ww >= W_) continue;
            float v = row[ww];
            if (dx <= 1) m0 += v * smw[(dy + 1) * 3 + (dx + 1)];
            if (dx >= 0) m1 += v * smw[(dy + 1) * 3 + dx];
        }
    }
    const float* sp = src + (size_t)p0 * 3;
    float2 s01 = *(const float2*)sp;
    float2 s23 = *(const float2*)(sp + 2);
    float2 s45 = *(const float2*)(sp + 4);
    float4 ov;
    ov.x = s01.y * m0 + p00;
    ov.y = s23.x * m0 + p01;
    ov.z = s45.x * m1 + p10;
    ov.w = s45.y * m1 + p11;
    *(float4*)&out[(size_t)p0 * 2] = ov;
}

// ---------------- launcher ----------------
extern "C" void kernel_launch(void* const* d_in, const int* in_sizes, int n_in,
                              void* d_out, int out_size) {
    const float* input = (const float*)d_in[0];
    const float* src   = (const float*)d_in[1];
    const float* iw1   = (const float*)d_in[2];
    const float* ib1   = (const float*)d_in[3];
    const float* iw2   = (const float*)d_in[4];
    const float* ib2   = (const float*)d_in[5];
    const float* ew1   = (const float*)d_in[6];
    const float* eb1   = (const float*)d_in[7];
    const float* ew2   = (const float*)d_in[8];
    const float* eb2   = (const float*)d_in[9];
    const float* fw1   = (const float*)d_in[10];
    const float* fw2   = (const float*)d_in[11];
    const float* cw    = (const float*)d_in[12];
    const float* cb    = (const float*)d_in[13];
    const float* pw1   = (const float*)d_in[14];
    const float* pb1   = (const float*)d_in[15];
    const float* pw2   = (const float*)d_in[16];
    const float* pb2   = (const float*)d_in[17];
    const float* mw    = (const float*)d_in[18];
    const float* mb    = (const float*)d_in[19];

    float *A, *Bp, *E, *S1, *S2p, *S2, *S3, *T;
    cudaGetSymbolAddress((void**)&A,   g_bufA);
    cudaGetSymbolAddress((void**)&Bp,  g_bufB);
    cudaGetSymbolAddress((void**)&E,   g_E);
    cudaGetSymbolAddress((void**)&S1,  g_S1);
    cudaGetSymbolAddress((void**)&S2p, g_S2p);
    cudaGetSymbolAddress((void**)&S2,  g_S2);
    cudaGetSymbolAddress((void**)&S3,  g_S3);
    cudaGetSymbolAddress((void**)&T,   g_T);

    k_tables<<<75, 256>>>();
    k_encode<<<Bb_ * NPIX / 512, 256>>>(input, src, iw1, ib1, iw2, ib2,
                                        ew1, eb1, ew2, eb2, A, E);
    for (int l = 0; l < 4; l++) {
        float* Ain  = (l & 1) ? Bp : A;
        float* Aout = (l & 1) ? A  : Bp;
        dim3 gfw(NROWS / FW_BM, 2);
        k_fft_w<<<gfw, 160>>>(Ain, E, S1);
        dim3 gfh(BC, KSPLIT);
        k_fft_h<<<gfh, 400>>>(S1, S2p);
        k_red<<<(BC * 1600 / 4 + 255) / 256, 256>>>(S2p, S2);
        k_mix<<<(Bb_ * C_ * NM * WN_ + 255) / 256, 256>>>(S2, fw1, fw2, l, S3);
        dim3 gih(BC, KSPLIT);
        k_ifft_h<<<gih, 400>>>(S3, T);
        dim3 g(W_ / 160, H_, Bb_);
        k_iw_conv<<<g, 160>>>(T, Ain, cw, cb, l, Aout, (l < 3) ? 1 : 0);
    }
    k_final<<<Bb_ * NPIX / 512, 256>>>(A, input, src, pw1, pb1, pw2, pb2,
                                       mw, mb, (float*)d_out);
}